// round 15
// baseline (speedup 1.0000x reference)
#include <cuda_runtime.h>

// PS-ROI-Align, fixed dims:
//   input: (N=4, C=490, H=100, W=100) f32
//   rois:  (K=2048, 5) f32  [batch, x1, y1, x2, y2]
//   out:   (K, 10, 7, 7) f32,  POOL=7, SCALE=1/16, GRID=2
//
// R11 structure (cp.async plane staging, 4 CTAs/SM, static-unrolled issue)
// + 2D band restriction: rows banded per (b,ph), columns banded per (b,pw)
// -> stages only the sub-rectangle any roi of this (b,ph,pw) can touch
// (~36% less DRAM traffic than full planes).

#define C_TOT   490
#define HH      100
#define WW      100
#define POOL    7
#define SSCALE  0.0625f
#define PLANE   (HH * WW)
#define K_ROIS  2048
#define NBATCH  4
#define MAXSW4  108                   // max smem row width in floats
#define SMEM_FLOATS (100 * MAXSW4)    // 43200 B worst case

__device__ int    g_count[NBATCH];
__device__ int    g_list[NBATCH][K_ROIS];
__device__ float4 g_par [NBATCH][K_ROIS];   // x1, y1, bsw, bsh
__device__ int    g_rowlo[NBATCH][POOL];
__device__ int    g_rowhi[NBATCH][POOL];
__device__ int    g_collo[NBATCH][POOL];    // min wbase (mult of 4)
__device__ int    g_colwb[NBATCH][POOL];    // max wbase

__global__ void prep_kernel(const float* __restrict__ rois)
{
    __shared__ int s_rlo[NBATCH][POOL], s_rhi[NBATCH][POOL];
    __shared__ int s_clo[NBATCH][POOL], s_cwb[NBATCH][POOL];
    int t = threadIdx.x;
    if (t < NBATCH) g_count[t] = 0;
    if (t < NBATCH * POOL) {
        int bb = t / POOL, pp = t % POOL;
        s_rlo[bb][pp] = HH - 1; s_rhi[bb][pp] = 0;
        s_clo[bb][pp] = WW - 1; s_cwb[bb][pp] = 0;
    }
    __syncthreads();
    for (int k = t; k < K_ROIS; k += blockDim.x) {
        const float* roi = rois + k * 5;
        int   b  = (int)roi[0];
        float x1 = roi[1] * SSCALE - 0.5f;
        float y1 = roi[2] * SSCALE - 0.5f;
        float x2 = roi[3] * SSCALE - 0.5f;
        float y2 = roi[4] * SSCALE - 0.5f;
        float bsw = (x2 - x1) * (1.0f / POOL);
        float bsh = (y2 - y1) * (1.0f / POOL);
        int i = atomicAdd(&g_count[b], 1);
        g_list[b][i] = k;
        g_par[b][i]  = make_float4(x1, y1, bsw, bsh);

        #pragma unroll
        for (int p = 0; p < POOL; ++p) {
            // rows for bin ph=p
            float ty0 = fmaxf(y1 + ((float)p + 0.25f) * bsh, 0.0f);
            float ty1 = fmaxf(y1 + ((float)p + 0.75f) * bsh, 0.0f);
            int yl0 = min((int)ty0, HH - 1);
            int yl1 = min((int)ty1, HH - 1);
            int yh1 = min(yl1 + 1, HH - 1);
            atomicMin(&s_rlo[b][p], yl0);
            atomicMax(&s_rhi[b][p], yh1);
            // cols for bin pw=p
            float tx0 = fmaxf(x1 + ((float)p + 0.25f) * bsw, 0.0f);
            int xl0 = min((int)tx0, WW - 1);
            int wb = xl0 & ~3;
            atomicMin(&s_clo[b][p], wb);
            atomicMax(&s_cwb[b][p], wb);
        }
    }
    __syncthreads();
    if (t < NBATCH * POOL) {
        int bb = t / POOL, pp = t % POOL;
        g_rowlo[bb][pp] = s_rlo[bb][pp];
        g_rowhi[bb][pp] = s_rhi[bb][pp];
        g_collo[bb][pp] = s_clo[bb][pp];
        g_colwb[bb][pp] = s_cwb[bb][pp];
    }
}

__global__ __launch_bounds__(256, 4) void psroi_main(
    const float* __restrict__ input,
    float* __restrict__ out)
{
    __shared__ float s_plane[SMEM_FLOATS];

    int r = blockIdx.x;          // channel / output slice index, 0..489
    int b = blockIdx.y;          // batch, 0..3
    int t = threadIdx.x;

    int pw = r % POOL;
    int ph = (r / POOL) % POOL;

    int lo   = g_rowlo[b][ph];
    int rows = g_rowhi[b][ph] - lo + 1;
    int cl   = g_collo[b][pw];                 // mult of 4
    int SWf  = g_colwb[b][pw] + 8 - cl + 1;    // needed floats per row (taps + window overrun)
    int SW4  = (SWf + 3) & ~3;                 // smem row stride (floats)
    int sw4q = SW4 >> 2;                       // float4 per smem row
    int avail4 = (WW - cl) >> 2;               // float4 available in gmem row
    int ld4  = min(sw4q, avail4);              // float4 actually loaded per row
    int total4 = rows * ld4;

    // ---- async banded load: gmem sub-rect -> smem, static-unrolled issue ----
    {
        const float* gbase = input + ((long)b * C_TOT + r) * PLANE + cl;
        #pragma unroll
        for (int i = 0; i < 10; ++i) {          // total4 <= 2500
            int j = t + (i << 8);
            if (j < total4) {
                int y = j / ld4;
                int c = j - y * ld4;
                const float4* src = (const float4*)(gbase + (lo + y) * WW) + c;
                float4* dst = (float4*)(s_plane + y * SW4) + c;
                unsigned saddr = (unsigned)__cvta_generic_to_shared(dst);
                asm volatile("cp.async.cg.shared.global [%0], [%1], 16;\n"
                             :: "r"(saddr), "l"(src) : "memory");
            }
        }
        asm volatile("cp.async.commit_group;\n" ::: "memory");
    }
    // zero smem tail columns (window float4s past the gmem row end); keeps
    // weight-0 taps away from NaN garbage.
    if (sw4q > ld4) {
        int tail4 = sw4q - ld4;                 // 1..2
        int ztot = rows * tail4;
        float4 Z4 = make_float4(0.f, 0.f, 0.f, 0.f);
        for (int j = t; j < ztot; j += 256) {
            int y = j / tail4;
            int c = j - y * tail4;
            ((float4*)(s_plane + y * SW4))[ld4 + c] = Z4;
        }
    }

    // block-uniform bin coordinates (computed while loads are in flight)
    float cpw0 = (float)pw + 0.25f, cpw1 = (float)pw + 0.75f;
    float cph0 = (float)ph + 0.25f, cph1 = (float)ph + 0.75f;
    int n = g_count[b];

    asm volatile("cp.async.wait_group 0;\n" ::: "memory");
    __syncthreads();

    for (int i = t; i < n; i += 256) {
        int    k = g_list[b][i];
        float4 P = g_par[b][i];
        float x1 = P.x, y1 = P.y, bsw = P.z, bsh = P.w;

        // ---- x taps ----
        float tx0 = fmaxf(x1 + cpw0 * bsw, 0.0f);
        float tx1 = fmaxf(x1 + cpw1 * bsw, 0.0f);
        int xl0 = min((int)tx0, WW - 1);
        int xl1 = min((int)tx1, WW - 1);
        int xh0 = min(xl0 + 1, WW - 1);
        int xh1 = min(xl1 + 1, WW - 1);
        float fx0 = (xl0 >= WW - 1) ? 0.0f : tx0 - (float)xl0;
        float fx1 = (xl1 >= WW - 1) ? 0.0f : tx1 - (float)xl1;

        // ---- y taps ----
        float ty0 = fmaxf(y1 + cph0 * bsh, 0.0f);
        float ty1 = fmaxf(y1 + cph1 * bsh, 0.0f);
        int yl0 = min((int)ty0, HH - 1);
        int yl1 = min((int)ty1, HH - 1);
        int yh0 = min(yl0 + 1, HH - 1);
        int yh1 = min(yl1 + 1, HH - 1);
        float fy0 = (yl0 >= HH - 1) ? 0.0f : ty0 - (float)yl0;
        float fy1 = (yl1 >= HH - 1) ? 0.0f : ty1 - (float)yl1;

        float a0 = 1.0f - fy0, a1 = fy0;
        float a2 = 1.0f - fy1, a3 = fy1;

        // ---- branch-free row dedup ----
        bool same_pair = (yl1 == yl0);
        bool shift_one = (yl1 == yh0);
        bool act2 = !same_pair;
        bool act3 = !same_pair && !shift_one;
        int  row2 = shift_one ? yh1 : yl1;
        float wr0 = a0 + (same_pair ? a2 : 0.0f);
        float wr1 = a1 + (same_pair ? a3 : (shift_one ? a2 : 0.0f));
        float wr2 = shift_one ? a3 : a2;
        float wr3 = a3;

        // ---- aligned x window (smem rows SW4-aligned, cl mult of 4) ----
        int wbase = xl0 & ~3;
        int o_l0 = xl0 - wbase, o_h0 = xh0 - wbase;
        int o_l1 = xl1 - wbase, o_h1 = xh1 - wbase;
        bool needB = (o_h1 > 3);
        bool needC = (o_h1 > 7);        // == 8

        const float* rowbase = s_plane + (wbase - cl);
        const float4* p0 = (const float4*)(rowbase + (yl0  - lo) * SW4);
        const float4* p1 = (const float4*)(rowbase + (yh0  - lo) * SW4);
        const float4* p2 = (const float4*)(rowbase + (row2 - lo) * SW4);
        const float4* p3 = (const float4*)(rowbase + (yh1  - lo) * SW4);

        // ---- predicated smem loads ----
        float4 Z  = make_float4(0.f, 0.f, 0.f, 0.f);
        float4 A0, A1, A2 = Z, A3 = Z, B0 = Z, B1 = Z, B2 = Z, B3 = Z;
        float  c0 = 0.f, c1 = 0.f, c2 = 0.f, c3 = 0.f;
        A0 = *p0;
        A1 = *p1;
        if (act2)          A2 = *p2;
        if (act3)          A3 = *p3;
        if (needB)         B0 = p0[1];
        if (needB)         B1 = p1[1];
        if (needB && act2) B2 = p2[1];
        if (needB && act3) B3 = p3[1];
        if (needC)         c0 = ((const float*)p0)[8];
        if (needC)         c1 = ((const float*)p1)[8];
        if (needC && act2) c2 = ((const float*)p2)[8];
        if (needC && act3) c3 = ((const float*)p3)[8];

        // x-weight vector over window floats 0..7 (tap 8 via C scalars)
        float w[8];
        #pragma unroll
        for (int j = 0; j < 8; ++j) {
            float v = (j == o_l0) ? (1.0f - fx0) : 0.0f;
            v += (j == o_h0) ? fx0 : 0.0f;
            v += (j == o_l1) ? (1.0f - fx1) : 0.0f;
            v += (j == o_h1) ? fx1 : 0.0f;
            w[j] = v;
        }

        float ax = wr0 * A0.x + wr1 * A1.x + wr2 * A2.x + wr3 * A3.x;
        float ay = wr0 * A0.y + wr1 * A1.y + wr2 * A2.y + wr3 * A3.y;
        float az = wr0 * A0.z + wr1 * A1.z + wr2 * A2.z + wr3 * A3.z;
        float aw = wr0 * A0.w + wr1 * A1.w + wr2 * A2.w + wr3 * A3.w;
        float bx = wr0 * B0.x + wr1 * B1.x + wr2 * B2.x + wr3 * B3.x;
        float by = wr0 * B0.y + wr1 * B1.y + wr2 * B2.y + wr3 * B3.y;
        float bz = wr0 * B0.z + wr1 * B1.z + wr2 * B2.z + wr3 * B3.z;
        float bw = wr0 * B0.w + wr1 * B1.w + wr2 * B2.w + wr3 * B3.w;
        float cc = wr0 * c0   + wr1 * c1   + wr2 * c2   + wr3 * c3;

        float acc = ax * w[0] + ay * w[1] + az * w[2] + aw * w[3]
                  + bx * w[4] + by * w[5] + bz * w[6] + bw * w[7]
                  + (needC ? cc * fx1 : 0.0f);

        out[k * C_TOT + r] = acc * 0.25f;
    }
}

extern "C" void kernel_launch(void* const* d_in, const int* in_sizes, int n_in,
                              void* d_out, int out_size)
{
    const float* input = (const float*)d_in[0];
    const float* rois  = (const float*)d_in[1];
    float* out = (float*)d_out;

    prep_kernel<<<1, 512>>>(rois);
    dim3 grid(C_TOT, NBATCH);
    psroi_main<<<grid, 256>>>(input, out);
}

// round 16
// speedup vs baseline: 1.0692x; 1.0692x over previous
#include <cuda_runtime.h>

// PS-ROI-Align, fixed dims:
//   input: (N=4, C=490, H=100, W=100) f32
//   rois:  (K=2048, 5) f32  [batch, x1, y1, x2, y2]
//   out:   (K, 10, 7, 7) f32,  POOL=7, SCALE=1/16, GRID=2
//
// R11 structure (cp.async staging, 4 CTAs/SM, static-unrolled batched issue)
// + per-(b,ph) row band: stage only rows [lo,hi] (contiguous!) -> ~24% less
// DRAM traffic. Prep uses register-local band accumulation + warp redux
// (no contended atomics).

#define C_TOT   490
#define HH      100
#define WW      100
#define POOL    7
#define SSCALE  0.0625f
#define PLANE   (HH * WW)
#define K_ROIS  2048
#define NBATCH  4

__device__ int    g_count[NBATCH];
__device__ int    g_list[NBATCH][K_ROIS];
__device__ float4 g_par [NBATCH][K_ROIS];   // x1, y1, bsw, bsh
__device__ int    g_rowlo[NBATCH][POOL];
__device__ int    g_rowhi[NBATCH][POOL];

__global__ void prep_kernel(const float* __restrict__ rois)
{
    __shared__ int s_lo[NBATCH][POOL], s_hi[NBATCH][POOL];
    int t = threadIdx.x;                    // 512 threads
    if (t < NBATCH) g_count[t] = 0;
    if (t < NBATCH * POOL) {
        s_lo[t / POOL][t % POOL] = HH - 1;
        s_hi[t / POOL][t % POOL] = 0;
    }
    __syncthreads();

    // register-local band accumulation (static indexing via b==bb predicates)
    int llo[NBATCH][POOL], lhi[NBATCH][POOL];
    #pragma unroll
    for (int bb = 0; bb < NBATCH; ++bb)
        #pragma unroll
        for (int p = 0; p < POOL; ++p) { llo[bb][p] = HH - 1; lhi[bb][p] = 0; }

    for (int k = t; k < K_ROIS; k += 512) {
        const float* roi = rois + k * 5;
        int   b  = (int)roi[0];
        float x1 = roi[1] * SSCALE - 0.5f;
        float y1 = roi[2] * SSCALE - 0.5f;
        float x2 = roi[3] * SSCALE - 0.5f;
        float y2 = roi[4] * SSCALE - 0.5f;
        float bsw = (x2 - x1) * (1.0f / POOL);
        float bsh = (y2 - y1) * (1.0f / POOL);
        int i = atomicAdd(&g_count[b], 1);
        g_list[b][i] = k;
        g_par[b][i]  = make_float4(x1, y1, bsw, bsh);

        #pragma unroll
        for (int p = 0; p < POOL; ++p) {
            float ty0 = fmaxf(y1 + ((float)p + 0.25f) * bsh, 0.0f);
            float ty1 = fmaxf(y1 + ((float)p + 0.75f) * bsh, 0.0f);
            int yl0 = min((int)ty0, HH - 1);
            int yl1 = min((int)ty1, HH - 1);
            int yh1 = min(yl1 + 1, HH - 1);
            #pragma unroll
            for (int bb = 0; bb < NBATCH; ++bb) {
                if (b == bb) {
                    llo[bb][p] = min(llo[bb][p], yl0);
                    lhi[bb][p] = max(lhi[bb][p], yh1);
                }
            }
        }
    }

    // warp-level reduction, then one atomic per warp per (b,p)
    #pragma unroll
    for (int bb = 0; bb < NBATCH; ++bb) {
        #pragma unroll
        for (int p = 0; p < POOL; ++p) {
            int lo = __reduce_min_sync(0xffffffffu, llo[bb][p]);
            int hi = __reduce_max_sync(0xffffffffu, lhi[bb][p]);
            if ((t & 31) == 0) {
                atomicMin(&s_lo[bb][p], lo);
                atomicMax(&s_hi[bb][p], hi);
            }
        }
    }
    __syncthreads();
    if (t < NBATCH * POOL) {
        g_rowlo[t / POOL][t % POOL] = s_lo[t / POOL][t % POOL];
        g_rowhi[t / POOL][t % POOL] = s_hi[t / POOL][t % POOL];
    }
}

__global__ __launch_bounds__(256, 4) void psroi_main(
    const float* __restrict__ input,
    float* __restrict__ out)
{
    __shared__ float s_plane[PLANE + 16];

    int r = blockIdx.x;          // channel / output slice index, 0..489
    int b = blockIdx.y;          // batch, 0..3
    int t = threadIdx.x;

    int pw = r % POOL;
    int ph = (r / POOL) % POOL;

    int lo   = g_rowlo[b][ph];
    int cnt4 = (g_rowhi[b][ph] - lo + 1) * (WW / 4);   // contiguous float4 count

    // ---- async banded load: contiguous gmem rows lo..hi -> smem ----
    {
        const float4* src = (const float4*)(input + ((long)b * C_TOT + r) * PLANE
                                            + (long)lo * WW);
        float4* dst = (float4*)s_plane;
        #pragma unroll
        for (int i = 0; i < 10; ++i) {                  // cnt4 <= 2500
            int j = t + (i << 8);
            if (j < cnt4) {
                unsigned saddr = (unsigned)__cvta_generic_to_shared(dst + j);
                asm volatile("cp.async.cg.shared.global [%0], [%1], 16;\n"
                             :: "r"(saddr), "l"(src + j) : "memory");
            }
        }
        asm volatile("cp.async.commit_group;\n" ::: "memory");
    }
    // zero pad past the band (B/C taps on last row may overrun by <16 floats)
    if (t < 16) s_plane[cnt4 * 4 + t] = 0.0f;

    // block-uniform bin coordinates (computed while loads are in flight)
    float cpw0 = (float)pw + 0.25f, cpw1 = (float)pw + 0.75f;
    float cph0 = (float)ph + 0.25f, cph1 = (float)ph + 0.75f;
    int n = g_count[b];

    asm volatile("cp.async.wait_group 0;\n" ::: "memory");
    __syncthreads();

    // virtual plane base: s_plane holds rows lo..hi
    const float* plane_v = s_plane - lo * WW;

    for (int i = t; i < n; i += 256) {
        int    k = g_list[b][i];
        float4 P = g_par[b][i];
        float x1 = P.x, y1 = P.y, bsw = P.z, bsh = P.w;

        // ---- x taps ----
        float tx0 = fmaxf(x1 + cpw0 * bsw, 0.0f);
        float tx1 = fmaxf(x1 + cpw1 * bsw, 0.0f);
        int xl0 = min((int)tx0, WW - 1);
        int xl1 = min((int)tx1, WW - 1);
        int xh0 = min(xl0 + 1, WW - 1);
        int xh1 = min(xl1 + 1, WW - 1);
        float fx0 = (xl0 >= WW - 1) ? 0.0f : tx0 - (float)xl0;
        float fx1 = (xl1 >= WW - 1) ? 0.0f : tx1 - (float)xl1;

        // ---- y taps ----
        float ty0 = fmaxf(y1 + cph0 * bsh, 0.0f);
        float ty1 = fmaxf(y1 + cph1 * bsh, 0.0f);
        int yl0 = min((int)ty0, HH - 1);
        int yl1 = min((int)ty1, HH - 1);
        int yh0 = min(yl0 + 1, HH - 1);
        int yh1 = min(yl1 + 1, HH - 1);
        float fy0 = (yl0 >= HH - 1) ? 0.0f : ty0 - (float)yl0;
        float fy1 = (yl1 >= HH - 1) ? 0.0f : ty1 - (float)yl1;

        float a0 = 1.0f - fy0, a1 = fy0;
        float a2 = 1.0f - fy1, a3 = fy1;

        // ---- branch-free row dedup ----
        bool same_pair = (yl1 == yl0);
        bool shift_one = (yl1 == yh0);
        bool act2 = !same_pair;
        bool act3 = !same_pair && !shift_one;
        int  row2 = shift_one ? yh1 : yl1;
        float wr0 = a0 + (same_pair ? a2 : 0.0f);
        float wr1 = a1 + (same_pair ? a3 : (shift_one ? a2 : 0.0f));
        float wr2 = shift_one ? a3 : a2;
        float wr3 = a3;

        // ---- aligned x window (rows are 400B -> 16B aligned) ----
        int wbase = xl0 & ~3;
        int o_l0 = xl0 - wbase, o_h0 = xh0 - wbase;
        int o_l1 = xl1 - wbase, o_h1 = xh1 - wbase;
        bool needB = (o_h1 > 3);
        bool needC = (o_h1 > 7);        // == 8

        const float* rowbase = plane_v + wbase;
        const float4* p0 = (const float4*)(rowbase + yl0 * WW);
        const float4* p1 = (const float4*)(rowbase + yh0 * WW);
        const float4* p2 = (const float4*)(rowbase + row2 * WW);
        const float4* p3 = (const float4*)(rowbase + yh1 * WW);

        // ---- predicated smem loads ----
        float4 Z  = make_float4(0.f, 0.f, 0.f, 0.f);
        float4 A0, A1, A2 = Z, A3 = Z, B0 = Z, B1 = Z, B2 = Z, B3 = Z;
        float  c0 = 0.f, c1 = 0.f, c2 = 0.f, c3 = 0.f;
        A0 = *p0;
        A1 = *p1;
        if (act2)          A2 = *p2;
        if (act3)          A3 = *p3;
        if (needB)         B0 = p0[1];
        if (needB)         B1 = p1[1];
        if (needB && act2) B2 = p2[1];
        if (needB && act3) B3 = p3[1];
        if (needC)         c0 = ((const float*)p0)[8];
        if (needC)         c1 = ((const float*)p1)[8];
        if (needC && act2) c2 = ((const float*)p2)[8];
        if (needC && act3) c3 = ((const float*)p3)[8];

        // x-weight vector over window floats 0..7 (tap 8 via C scalars)
        float w[8];
        #pragma unroll
        for (int j = 0; j < 8; ++j) {
            float v = (j == o_l0) ? (1.0f - fx0) : 0.0f;
            v += (j == o_h0) ? fx0 : 0.0f;
            v += (j == o_l1) ? (1.0f - fx1) : 0.0f;
            v += (j == o_h1) ? fx1 : 0.0f;
            w[j] = v;
        }

        float ax = wr0 * A0.x + wr1 * A1.x + wr2 * A2.x + wr3 * A3.x;
        float ay = wr0 * A0.y + wr1 * A1.y + wr2 * A2.y + wr3 * A3.y;
        float az = wr0 * A0.z + wr1 * A1.z + wr2 * A2.z + wr3 * A3.z;
        float aw = wr0 * A0.w + wr1 * A1.w + wr2 * A2.w + wr3 * A3.w;
        float bx = wr0 * B0.x + wr1 * B1.x + wr2 * B2.x + wr3 * B3.x;
        float by = wr0 * B0.y + wr1 * B1.y + wr2 * B2.y + wr3 * B3.y;
        float bz = wr0 * B0.z + wr1 * B1.z + wr2 * B2.z + wr3 * B3.z;
        float bw = wr0 * B0.w + wr1 * B1.w + wr2 * B2.w + wr3 * B3.w;
        float cc = wr0 * c0   + wr1 * c1   + wr2 * c2   + wr3 * c3;

        float acc = ax * w[0] + ay * w[1] + az * w[2] + aw * w[3]
                  + bx * w[4] + by * w[5] + bz * w[6] + bw * w[7]
                  + (needC ? cc * fx1 : 0.0f);

        out[k * C_TOT + r] = acc * 0.25f;
    }
}

extern "C" void kernel_launch(void* const* d_in, const int* in_sizes, int n_in,
                              void* d_out, int out_size)
{
    const float* input = (const float*)d_in[0];
    const float* rois  = (const float*)d_in[1];
    float* out = (float*)d_out;

    prep_kernel<<<1, 512>>>(rois);
    dim3 grid(C_TOT, NBATCH);
    psroi_main<<<grid, 256>>>(input, out);
}

// round 17
// speedup vs baseline: 1.4184x; 1.3265x over previous
#include <cuda_runtime.h>

// PS-ROI-Align, fixed dims:
//   input: (N=4, C=490, H=100, W=100) f32
//   rois:  (K=2048, 5) f32  [batch, x1, y1, x2, y2]
//   out:   (K, 10, 7, 7) f32,  POOL=7, SCALE=1/16, GRID=2
//
// Main (unchanged from best): cp.async staging of per-(b,ph) row band,
// 4 CTAs/SM, static-unrolled batched issue, predicated minimal tap set.
// Prep (fixed): 29 parallel blocks — 28 per-bin band reductions with pure
// register min/max + warp redux (no local arrays -> no spills), 1 block
// for batch compaction.

#define C_TOT   490
#define HH      100
#define WW      100
#define POOL    7
#define SSCALE  0.0625f
#define PLANE   (HH * WW)
#define K_ROIS  2048
#define NBATCH  4

__device__ int    g_count[NBATCH];
__device__ int    g_list[NBATCH][K_ROIS];
__device__ float4 g_par [NBATCH][K_ROIS];   // x1, y1, bsw, bsh
__device__ int    g_rowlo[NBATCH][POOL];
__device__ int    g_rowhi[NBATCH][POOL];

__global__ __launch_bounds__(256) void prep_kernel(const float* __restrict__ rois)
{
    int blk = blockIdx.x;
    int t = threadIdx.x;

    if (blk < NBATCH * POOL) {
        // ---- band reduction for bin (b, p): 2 registers, no arrays ----
        int b = blk / POOL;
        int p = blk - b * POOL;
        float fp0 = (float)p + 0.25f;
        float fp1 = (float)p + 0.75f;

        int mlo = HH - 1, mhi = 0;
        for (int k = t; k < K_ROIS; k += 256) {
            const float* roi = rois + k * 5;
            int bb = (int)__ldg(roi + 0);
            if (bb == b) {
                float y1  = __ldg(roi + 2) * SSCALE - 0.5f;
                float y2  = __ldg(roi + 4) * SSCALE - 0.5f;
                float bsh = (y2 - y1) * (1.0f / POOL);
                float ty0 = fmaxf(y1 + fp0 * bsh, 0.0f);
                float ty1 = fmaxf(y1 + fp1 * bsh, 0.0f);
                int yl0 = min((int)ty0, HH - 1);
                int yl1 = min((int)ty1, HH - 1);
                int yh1 = min(yl1 + 1, HH - 1);
                mlo = min(mlo, yl0);
                mhi = max(mhi, yh1);
            }
        }
        mlo = __reduce_min_sync(0xffffffffu, mlo);
        mhi = __reduce_max_sync(0xffffffffu, mhi);

        __shared__ int s_lo[8], s_hi[8];
        int w = t >> 5;
        if ((t & 31) == 0) { s_lo[w] = mlo; s_hi[w] = mhi; }
        __syncthreads();
        if (t == 0) {
            int lo = s_lo[0], hi = s_hi[0];
            #pragma unroll
            for (int i = 1; i < 8; ++i) {
                lo = min(lo, s_lo[i]);
                hi = max(hi, s_hi[i]);
            }
            if (hi < lo) { lo = 0; hi = 0; }   // empty batch guard
            g_rowlo[b][p] = lo;
            g_rowhi[b][p] = hi;
        }
    } else {
        // ---- compaction block ----
        if (t < NBATCH) g_count[t] = 0;
        __syncthreads();
        for (int k = t; k < K_ROIS; k += 256) {
            const float* roi = rois + k * 5;
            int   b  = (int)__ldg(roi + 0);
            float x1 = __ldg(roi + 1) * SSCALE - 0.5f;
            float y1 = __ldg(roi + 2) * SSCALE - 0.5f;
            float x2 = __ldg(roi + 3) * SSCALE - 0.5f;
            float y2 = __ldg(roi + 4) * SSCALE - 0.5f;
            int i = atomicAdd(&g_count[b], 1);
            g_list[b][i] = k;
            g_par[b][i]  = make_float4(x1, y1,
                                       (x2 - x1) * (1.0f / POOL),
                                       (y2 - y1) * (1.0f / POOL));
        }
    }
}

__global__ __launch_bounds__(256, 4) void psroi_main(
    const float* __restrict__ input,
    float* __restrict__ out)
{
    __shared__ float s_plane[PLANE + 16];

    int r = blockIdx.x;          // channel / output slice index, 0..489
    int b = blockIdx.y;          // batch, 0..3
    int t = threadIdx.x;

    int pw = r % POOL;
    int ph = (r / POOL) % POOL;

    int lo   = g_rowlo[b][ph];
    int cnt4 = (g_rowhi[b][ph] - lo + 1) * (WW / 4);   // contiguous float4 count

    // ---- async banded load: contiguous gmem rows lo..hi -> smem ----
    {
        const float4* src = (const float4*)(input + ((long)b * C_TOT + r) * PLANE
                                            + (long)lo * WW);
        float4* dst = (float4*)s_plane;
        #pragma unroll
        for (int i = 0; i < 10; ++i) {                  // cnt4 <= 2500
            int j = t + (i << 8);
            if (j < cnt4) {
                unsigned saddr = (unsigned)__cvta_generic_to_shared(dst + j);
                asm volatile("cp.async.cg.shared.global [%0], [%1], 16;\n"
                             :: "r"(saddr), "l"(src + j) : "memory");
            }
        }
        asm volatile("cp.async.commit_group;\n" ::: "memory");
    }
    // zero pad past the band (B/C taps on last row may overrun by <16 floats)
    if (t < 16) s_plane[cnt4 * 4 + t] = 0.0f;

    // block-uniform bin coordinates (computed while loads are in flight)
    float cpw0 = (float)pw + 0.25f, cpw1 = (float)pw + 0.75f;
    float cph0 = (float)ph + 0.25f, cph1 = (float)ph + 0.75f;
    int n = g_count[b];

    asm volatile("cp.async.wait_group 0;\n" ::: "memory");
    __syncthreads();

    // virtual plane base: s_plane holds rows lo..hi
    const float* plane_v = s_plane - lo * WW;

    for (int i = t; i < n; i += 256) {
        int    k = g_list[b][i];
        float4 P = g_par[b][i];
        float x1 = P.x, y1 = P.y, bsw = P.z, bsh = P.w;

        // ---- x taps ----
        float tx0 = fmaxf(x1 + cpw0 * bsw, 0.0f);
        float tx1 = fmaxf(x1 + cpw1 * bsw, 0.0f);
        int xl0 = min((int)tx0, WW - 1);
        int xl1 = min((int)tx1, WW - 1);
        int xh0 = min(xl0 + 1, WW - 1);
        int xh1 = min(xl1 + 1, WW - 1);
        float fx0 = (xl0 >= WW - 1) ? 0.0f : tx0 - (float)xl0;
        float fx1 = (xl1 >= WW - 1) ? 0.0f : tx1 - (float)xl1;

        // ---- y taps ----
        float ty0 = fmaxf(y1 + cph0 * bsh, 0.0f);
        float ty1 = fmaxf(y1 + cph1 * bsh, 0.0f);
        int yl0 = min((int)ty0, HH - 1);
        int yl1 = min((int)ty1, HH - 1);
        int yh0 = min(yl0 + 1, HH - 1);
        int yh1 = min(yl1 + 1, HH - 1);
        float fy0 = (yl0 >= HH - 1) ? 0.0f : ty0 - (float)yl0;
        float fy1 = (yl1 >= HH - 1) ? 0.0f : ty1 - (float)yl1;

        float a0 = 1.0f - fy0, a1 = fy0;
        float a2 = 1.0f - fy1, a3 = fy1;

        // ---- branch-free row dedup ----
        bool same_pair = (yl1 == yl0);
        bool shift_one = (yl1 == yh0);
        bool act2 = !same_pair;
        bool act3 = !same_pair && !shift_one;
        int  row2 = shift_one ? yh1 : yl1;
        float wr0 = a0 + (same_pair ? a2 : 0.0f);
        float wr1 = a1 + (same_pair ? a3 : (shift_one ? a2 : 0.0f));
        float wr2 = shift_one ? a3 : a2;
        float wr3 = a3;

        // ---- aligned x window (rows are 400B -> 16B aligned) ----
        int wbase = xl0 & ~3;
        int o_l0 = xl0 - wbase, o_h0 = xh0 - wbase;
        int o_l1 = xl1 - wbase, o_h1 = xh1 - wbase;
        bool needB = (o_h1 > 3);
        bool needC = (o_h1 > 7);        // == 8

        const float* rowbase = plane_v + wbase;
        const float4* p0 = (const float4*)(rowbase + yl0 * WW);
        const float4* p1 = (const float4*)(rowbase + yh0 * WW);
        const float4* p2 = (const float4*)(rowbase + row2 * WW);
        const float4* p3 = (const float4*)(rowbase + yh1 * WW);

        // ---- predicated smem loads ----
        float4 Z  = make_float4(0.f, 0.f, 0.f, 0.f);
        float4 A0, A1, A2 = Z, A3 = Z, B0 = Z, B1 = Z, B2 = Z, B3 = Z;
        float  c0 = 0.f, c1 = 0.f, c2 = 0.f, c3 = 0.f;
        A0 = *p0;
        A1 = *p1;
        if (act2)          A2 = *p2;
        if (act3)          A3 = *p3;
        if (needB)         B0 = p0[1];
        if (needB)         B1 = p1[1];
        if (needB && act2) B2 = p2[1];
        if (needB && act3) B3 = p3[1];
        if (needC)         c0 = ((const float*)p0)[8];
        if (needC)         c1 = ((const float*)p1)[8];
        if (needC && act2) c2 = ((const float*)p2)[8];
        if (needC && act3) c3 = ((const float*)p3)[8];

        // x-weight vector over window floats 0..7 (tap 8 via C scalars)
        float w[8];
        #pragma unroll
        for (int j = 0; j < 8; ++j) {
            float v = (j == o_l0) ? (1.0f - fx0) : 0.0f;
            v += (j == o_h0) ? fx0 : 0.0f;
            v += (j == o_l1) ? (1.0f - fx1) : 0.0f;
            v += (j == o_h1) ? fx1 : 0.0f;
            w[j] = v;
        }

        float ax = wr0 * A0.x + wr1 * A1.x + wr2 * A2.x + wr3 * A3.x;
        float ay = wr0 * A0.y + wr1 * A1.y + wr2 * A2.y + wr3 * A3.y;
        float az = wr0 * A0.z + wr1 * A1.z + wr2 * A2.z + wr3 * A3.z;
        float aw = wr0 * A0.w + wr1 * A1.w + wr2 * A2.w + wr3 * A3.w;
        float bx = wr0 * B0.x + wr1 * B1.x + wr2 * B2.x + wr3 * B3.x;
        float by = wr0 * B0.y + wr1 * B1.y + wr2 * B2.y + wr3 * B3.y;
        float bz = wr0 * B0.z + wr1 * B1.z + wr2 * B2.z + wr3 * B3.z;
        float bw = wr0 * B0.w + wr1 * B1.w + wr2 * B2.w + wr3 * B3.w;
        float cc = wr0 * c0   + wr1 * c1   + wr2 * c2   + wr3 * c3;

        float acc = ax * w[0] + ay * w[1] + az * w[2] + aw * w[3]
                  + bx * w[4] + by * w[5] + bz * w[6] + bw * w[7]
                  + (needC ? cc * fx1 : 0.0f);

        out[k * C_TOT + r] = acc * 0.25f;
    }
}

extern "C" void kernel_launch(void* const* d_in, const int* in_sizes, int n_in,
                              void* d_out, int out_size)
{
    const float* input = (const float*)d_in[0];
    const float* rois  = (const float*)d_in[1];
    float* out = (float*)d_out;

    prep_kernel<<<NBATCH * POOL + 1, 256>>>(rois);
    dim3 grid(C_TOT, NBATCH);
    psroi_main<<<grid, 256>>>(input, out);
}